// round 7
// baseline (speedup 1.0000x reference)
#include <cuda_runtime.h>
#include <math.h>

#define NN 50000
#define EE 500000
#define DD 64
#define GG 50
#define NPG 1000   // nodes per graph
#define CSRB 196   // blocks in fused CSR kernel (all-resident => safe grid barrier)
#define XPAD 132   // sXT row stride: 16B-aligned rows, conflict-free float4 reads

// ---------------- scratch (static device globals; no runtime alloc) ----------------
__device__ __align__(16) float g_hr  [NN*DD];   // raw (pre-pairnorm) node features
__device__ __align__(16) float g_a   [NN*DD];
__device__ __align__(16) float g_b   [NN*DD];
__device__ __align__(16) float g_aggr[NN*DD];
__device__ int   g_cnt[NN];
__device__ int   g_rowptr[NN+1];
__device__ __align__(8) int2 g_csr[EE];         // {src, float_as_int(dist)}
__device__ __align__(16) float g_stats[DD+1];   // colsum[64], sumsq
__device__ __align__(16) float g_norm [DD+1];   // mu[64], inv
__device__ int   g_bsum[256];
__device__ int   g_barcnt = 0;
__device__ int   g_bargen = 0;
__device__ int   g_done   = 0;

// ---- software grid barrier (valid: all CSRB blocks resident) ----
__device__ __forceinline__ void grid_barrier() {
    __syncthreads();
    if (threadIdx.x == 0) {
        __threadfence();
        int gen = *(volatile int*)&g_bargen;
        if (atomicAdd(&g_barcnt, 1) == (int)gridDim.x - 1) {
            atomicExch(&g_barcnt, 0);
            __threadfence();
            atomicAdd(&g_bargen, 1);
        } else {
            while (*(volatile int*)&g_bargen == gen) { }
        }
        __threadfence();
    }
    __syncthreads();
}

// ---------------- fused: CSR build + input embedding + norm/stats init ----------------
__global__ void __launch_bounds__(256) k_csr_build(const int*   __restrict__ ei,
                                                   const float* __restrict__ pos,
                                                   const float* __restrict__ hin,
                                                   const float* __restrict__ Wemb,
                                                   const float* __restrict__ bemb) {
    __shared__ int s[256];
    int tid = threadIdx.x;
    int bid = blockIdx.x;
    int gt  = bid * 256 + tid;

    if (gt < 64)  { g_norm[gt] = 0.f; g_stats[gt] = 0.f; }
    if (gt == 64) { g_norm[64] = 1.f; g_stats[64] = 0.f; g_done = 0; }

    if (gt < NN) g_cnt[gt] = 0;
    grid_barrier();

    for (int e = gt; e < EE; e += CSRB * 256)
        atomicAdd(&g_cnt[ei[EE + e]], 1);
    grid_barrier();

    {
        int c = (gt < NN) ? g_cnt[gt] : 0;
        s[tid] = c;
        __syncthreads();
        #pragma unroll
        for (int off = 1; off < 256; off <<= 1) {
            int t = 0;
            if (tid >= off) t = s[tid - off];
            __syncthreads();
            s[tid] += t;
            __syncthreads();
        }
        if (gt < NN) g_rowptr[gt] = s[tid] - c;
        if (tid == 255) g_bsum[bid] = s[255];
    }
    grid_barrier();

    if (bid == 0) {
        int c = (tid < CSRB) ? g_bsum[tid] : 0;
        s[tid] = c;
        __syncthreads();
        #pragma unroll
        for (int off = 1; off < 256; off <<= 1) {
            int t = 0;
            if (tid >= off) t = s[tid - off];
            __syncthreads();
            s[tid] += t;
            __syncthreads();
        }
        if (tid < CSRB) g_bsum[tid] = s[tid] - c;
    }
    grid_barrier();

    if (gt < NN) {
        int r = g_rowptr[gt] + g_bsum[bid];
        g_rowptr[gt] = r;
        g_cnt[gt] = r;
    }
    if (gt == 0) g_rowptr[NN] = EE;
    grid_barrier();

    for (int e = gt; e < EE; e += CSRB * 256) {
        int sn = ei[e];
        int d  = ei[EE + e];
        int p  = atomicAdd(&g_cnt[d], 1);
        float dx = pos[2*d]   - pos[2*sn];
        float dy = pos[2*d+1] - pos[2*sn+1];
        g_csr[p] = make_int2(sn, __float_as_int(sqrtf(dx*dx + dy*dy)));
    }

    int lane = tid & 31;
    int c0   = lane * 2;
    for (int w = gt >> 5; w < NN; w += (CSRB*256) >> 5) {
        float v0 = hin[w*5+0], v1 = hin[w*5+1], v2 = hin[w*5+2],
              v3 = hin[w*5+3], v4 = hin[w*5+4];
        #pragma unroll
        for (int j = 0; j < 2; j++) {
            int c = c0 + j;
            float acc = bemb[c] + v0*Wemb[c] + v1*Wemb[64+c] + v2*Wemb[128+c]
                                + v3*Wemb[192+c] + v4*Wemb[256+c];
            g_hr[w*64+c] = fmaxf(acc, 0.f);
        }
    }
}

// ---- shared staging helper: X^T chunk (32 k x 128 nodes) with optional pairnorm ----
__device__ __forceinline__ void stage_xt(float* sXT, const float* __restrict__ Xsrc,
                                         int base, int koff, bool donorm, float inv) {
    int tid = threadIdx.x;
    #pragma unroll
    for (int it = 0; it < 4; it++) {
        int idx = tid + 256*it;          // 1024 float4 = 128 nodes x 8 float4
        int nl  = idx >> 3;
        int kq  = idx & 7;
        int n   = base + nl;
        float4 v = make_float4(0.f,0.f,0.f,0.f);
        if (n < NN) v = *(const float4*)&Xsrc[n*64 + koff + kq*4];
        if (donorm) {
            float4 mu = *(const float4*)&g_norm[koff + kq*4];
            v.x = (v.x - mu.x)*inv; v.y = (v.y - mu.y)*inv;
            v.z = (v.z - mu.z)*inv; v.w = (v.w - mu.w)*inv;
        }
        sXT[(kq*4+0)*XPAD + nl] = v.x;
        sXT[(kq*4+1)*XPAD + nl] = v.y;
        sXT[(kq*4+2)*XPAD + nl] = v.z;
        sXT[(kq*4+3)*XPAD + nl] = v.w;
    }
}

// ---------------- GEMM: [a|b] = pairnorm(hr) @ Wm_remap  (3 LDS.128 / 32 FMA) ----------------
__global__ void __launch_bounds__(256) k_gemm_ab(const float* __restrict__ Wm) {
    __shared__ __align__(16) float sXT[32*XPAD];
    __shared__ __align__(16) float sW [32*64];
    int tid  = threadIdx.x;
    int base = blockIdx.x * 128;
    float inv = g_norm[64];
    int nq = tid & 31;               // node-quad: nodes 4nq..4nq+3
    int cg = tid >> 5;               // warp id: cols cg*8..+7 (warp-uniform)

    #pragma unroll
    for (int half = 0; half < 2; half++) {
        float acc[4][8];
        #pragma unroll
        for (int i = 0; i < 4; i++)
            #pragma unroll
            for (int j = 0; j < 8; j++) acc[i][j] = 0.f;
        int rbase = half ? 64 : 0;

        for (int kc = 0; kc < 64; kc += 32) {
            __syncthreads();
            stage_xt(sXT, g_hr, base, kc, true, inv);
            #pragma unroll
            for (int it = 0; it < 8; it++) {
                int idx = tid + 256*it;  // 2048 floats: [32 kk][64 c]
                int c   = idx & 63;
                int kk  = idx >> 6;
                sW[kk*64 + c] = Wm[(rbase + kc + kk)*64 + c];
            }
            __syncthreads();
            #pragma unroll
            for (int kk = 0; kk < 32; kk++) {
                float4 xv = *(const float4*)&sXT[kk*XPAD + nq*4];
                float4 wA = *(const float4*)&sW[kk*64 + cg*8];
                float4 wB = *(const float4*)&sW[kk*64 + cg*8 + 4];
                float xs[4] = {xv.x, xv.y, xv.z, xv.w};
                float wv[8] = {wA.x,wA.y,wA.z,wA.w,wB.x,wB.y,wB.z,wB.w};
                #pragma unroll
                for (int i = 0; i < 4; i++)
                    #pragma unroll
                    for (int j = 0; j < 8; j++)
                        acc[i][j] = fmaf(xs[i], wv[j], acc[i][j]);
            }
        }
        float* Out = half ? g_b : g_a;
        #pragma unroll
        for (int i = 0; i < 4; i++) {
            int n = base + nq*4 + i;
            if (n < NN) {
                *(float4*)&Out[n*64 + cg*8]     = make_float4(acc[i][0],acc[i][1],acc[i][2],acc[i][3]);
                *(float4*)&Out[n*64 + cg*8 + 4] = make_float4(acc[i][4],acc[i][5],acc[i][6],acc[i][7]);
            }
        }
    }
}

// ---------------- per-node edge gather (standalone, MLP=8) ----------------
__global__ void __launch_bounds__(256) k_gather(const float* __restrict__ Wm,
                                                const float* __restrict__ bm) {
    int gw   = (blockIdx.x*blockDim.x + threadIdx.x) >> 5;
    int lane = threadIdx.x & 31;
    int c0 = lane*2;
    float wdx = Wm[128*64 + c0], wdy = Wm[128*64 + c0 + 1];
    float2 av = *(const float2*)&g_a[gw*64 + c0];
    float pax = av.x + bm[c0];
    float pay = av.y + bm[c0+1];
    float ax = 0.f, ay = 0.f;
    int st = g_rowptr[gw], en = g_rowptr[gw+1];

    for (int eb = st; eb < en; eb += 8) {
        int mm = en - eb; if (mm > 8) mm = 8;
        int2 ed = make_int2(0, 0);
        if (lane < mm) ed = g_csr[eb + lane];
        float2 bv[8];
        float  dv[8];
        #pragma unroll
        for (int j = 0; j < 8; j++) {
            int sidx = __shfl_sync(0xffffffffu, ed.x, j);
            int dbit = __shfl_sync(0xffffffffu, ed.y, j);
            dv[j] = __int_as_float(dbit);
            if (j < mm) bv[j] = *(const float2*)&g_b[sidx*64 + c0];
        }
        #pragma unroll
        for (int j = 0; j < 8; j++) {
            if (j < mm) {
                ax += fmaxf(pax + bv[j].x + dv[j]*wdx, 0.f);
                ay += fmaxf(pay + bv[j].y + dv[j]*wdy, 0.f);
            }
        }
    }
    *(float2*)&g_aggr[gw*64 + c0] = make_float2(ax, ay);
}

// ---------------- update GEMM (3 LDS.128 / 32 FMA) + stats + finalize ----------------
__global__ void __launch_bounds__(256) k_gemm_upd(const float* __restrict__ Wu,
                                                  const float* __restrict__ bu) {
    __shared__ __align__(16) float sXT[32*XPAD];
    __shared__ __align__(16) float sW [32*64];
    int tid  = threadIdx.x;
    int base = blockIdx.x * 128;
    float inv = g_norm[64];
    int nq = tid & 31;
    int cg = tid >> 5;               // warp-uniform col group (8 cols)
    float acc[4][8];
    #pragma unroll
    for (int i = 0; i < 4; i++)
        #pragma unroll
        for (int j = 0; j < 8; j++) acc[i][j] = 0.f;

    for (int kc = 0; kc < 128; kc += 32) {
        __syncthreads();
        const bool fromH = (kc < 64);
        stage_xt(sXT, fromH ? g_hr : g_aggr, base, kc & 63, fromH, inv);
        #pragma unroll
        for (int it = 0; it < 8; it++) {
            int idx = tid + 256*it;
            int c   = idx & 63;
            int kk  = idx >> 6;
            sW[kk*64 + c] = Wu[(kc + kk)*64 + c];
        }
        __syncthreads();
        #pragma unroll
        for (int kk = 0; kk < 32; kk++) {
            float4 xv = *(const float4*)&sXT[kk*XPAD + nq*4];
            float4 wA = *(const float4*)&sW[kk*64 + cg*8];
            float4 wB = *(const float4*)&sW[kk*64 + cg*8 + 4];
            float xs[4] = {xv.x, xv.y, xv.z, xv.w};
            float wv[8] = {wA.x,wA.y,wA.z,wA.w,wB.x,wB.y,wB.z,wB.w};
            #pragma unroll
            for (int i = 0; i < 4; i++)
                #pragma unroll
                for (int j = 0; j < 8; j++)
                    acc[i][j] = fmaf(xs[i], wv[j], acc[i][j]);
        }
    }

    // epilogue: bias+relu, store, stats
    int c0 = cg*8;
    float4 bA = *(const float4*)&bu[c0];
    float4 bB = *(const float4*)&bu[c0+4];
    float bvv[8] = {bA.x,bA.y,bA.z,bA.w,bB.x,bB.y,bB.z,bB.w};
    float ls[8] = {0,0,0,0,0,0,0,0};
    float lss = 0.f;
    #pragma unroll
    for (int i = 0; i < 4; i++) {
        int n = base + nq*4 + i;
        if (n < NN) {
            float o[8];
            #pragma unroll
            for (int j = 0; j < 8; j++) {
                o[j] = fmaxf(acc[i][j] + bvv[j], 0.f);
                ls[j] += o[j];
                lss   += o[j]*o[j];
            }
            *(float4*)&g_hr[n*64 + c0]     = make_float4(o[0],o[1],o[2],o[3]);
            *(float4*)&g_hr[n*64 + c0 + 4] = make_float4(o[4],o[5],o[6],o[7]);
        }
    }
    // full-warp reduce (cg uniform across warp)
    #pragma unroll
    for (int off = 16; off > 0; off >>= 1) {
        #pragma unroll
        for (int j = 0; j < 8; j++)
            ls[j] += __shfl_down_sync(0xffffffffu, ls[j], off);
        lss += __shfl_down_sync(0xffffffffu, lss, off);
    }
    if ((tid & 31) == 0) {
        #pragma unroll
        for (int j = 0; j < 8; j++) atomicAdd(&g_stats[c0 + j], ls[j]);
        atomicAdd(&g_stats[64], lss);
    }

    // last block finalizes g_norm, re-arms stats
    __shared__ int isLast;
    __threadfence();
    __syncthreads();
    if (tid == 0)
        isLast = (atomicAdd(&g_done, 1) == (int)gridDim.x - 1) ? 1 : 0;
    __syncthreads();
    if (isLast) {
        __shared__ float spart[2];
        if (tid < 64) {
            float mu = g_stats[tid] * (1.0f/NN);
            g_norm[tid] = mu;
            float m2 = mu*mu;
            #pragma unroll
            for (int off = 16; off > 0; off >>= 1)
                m2 += __shfl_down_sync(0xffffffffu, m2, off);
            if ((tid & 31) == 0) spart[tid >> 5] = m2;
        }
        __syncthreads();
        if (tid == 0) {
            float musq = spart[0] + spart[1];
            g_norm[64] = 1.0f / sqrtf(1e-5f + g_stats[64]*(1.0f/NN) - musq);
            g_done = 0;
        }
        __syncthreads();
        if (tid < 65) g_stats[tid] = 0.f;
    }
}

// ---------------- per-graph max pool (raw h + lazy norm) + tiny MLP ----------------
__global__ void k_pool(const float* __restrict__ W1, const float* __restrict__ b1,
                       const float* __restrict__ W2, const float* __restrict__ b2,
                       float* __restrict__ out) {
    __shared__ float red[4][64];
    __shared__ float hg[64];
    __shared__ float z[64];
    int g   = blockIdx.x;
    int tid = threadIdx.x;
    int c     = tid & 63;
    int chunk = tid >> 6;
    float m = -3.4e38f;
    int nbeg = g*NPG + chunk*(NPG/4);
    for (int i = 0; i < NPG/4; i++)
        m = fmaxf(m, g_hr[(nbeg + i)*64 + c]);
    red[chunk][c] = m;
    __syncthreads();
    if (tid < 64) {
        float mr = fmaxf(fmaxf(red[0][tid], red[1][tid]),
                         fmaxf(red[2][tid], red[3][tid]));
        hg[tid] = (mr - g_norm[tid]) * g_norm[64];
    }
    __syncthreads();
    if (tid < 64) {
        float acc = b1[tid];
        for (int k = 0; k < 64; k++) acc = fmaf(hg[k], W1[k*64 + tid], acc);
        z[tid] = fmaxf(acc, 0.f);
    }
    __syncthreads();
    if (tid < 2) {
        float acc = b2[tid];
        for (int k = 0; k < 64; k++) acc = fmaf(z[k], W2[k*2 + tid], acc);
        out[g*2 + tid] = acc;
    }
}

// ---------------- launch ----------------
extern "C" void kernel_launch(void* const* d_in, const int* in_sizes, int n_in,
                              void* d_out, int out_size) {
    const float* h_in = (const float*)d_in[0];
    const float* pos  = (const float*)d_in[1];
    const int*   ei   = (const int*)  d_in[2];
    // d_in[3] = batch — contiguous 1000-node graphs, unused
    const float* Wemb = (const float*)d_in[4];
    const float* bemb = (const float*)d_in[5];
    const float* msgW = (const float*)d_in[6];
    const float* msgb = (const float*)d_in[7];
    const float* updW = (const float*)d_in[8];
    const float* updb = (const float*)d_in[9];
    const float* W1   = (const float*)d_in[10];
    const float* b1   = (const float*)d_in[11];
    const float* W2   = (const float*)d_in[12];
    const float* b2   = (const float*)d_in[13];
    float* out = (float*)d_out;

    k_csr_build<<<CSRB, 256>>>(ei, pos, h_in, Wemb, bemb);

    for (int l = 0; l < 2; l++) {
        const float* Wm = msgW + l*129*64;
        const float* bm = msgb + l*64;
        const float* Wu = updW + l*128*64;
        const float* bu = updb + l*64;
        k_gemm_ab <<<391, 256>>>(Wm);
        k_gather  <<<6250, 256>>>(Wm, bm);
        k_gemm_upd<<<391, 256>>>(Wu, bu);
    }

    k_pool<<<50, 256>>>(W1, b1, W2, b2, out);
}

// round 9
// speedup vs baseline: 1.1880x; 1.1880x over previous
#include <cuda_runtime.h>
#include <cuda_bf16.h>
#include <mma.h>
#include <math.h>
#include <stdint.h>

using namespace nvcuda;

#define NN 50000
#define EE 500000
#define DD 64
#define GG 50
#define NPG 1000
#define CSRB 196
#define XLD 80     // bf16 X tile leading dim (rows 128) -> 160B rows, 32B-aligned tiles
#define WLD_AB 136 // bf16 W tile ld for 128-col ab weights
#define WLD_UP 72  // bf16 W tile ld for 64-col upd weights
#define OLD 68     // fp32 out-tile ld for upd epilogue

// ---------------- scratch ----------------
__device__ __align__(16) float g_hr  [NN*DD];
__device__ __align__(16) float g_a   [NN*DD];
__device__ __align__(16) float g_b   [NN*DD];
__device__ __align__(16) float g_aggr[NN*DD];
__device__ int   g_cnt[NN];
__device__ int   g_rowptr[NN+1];
__device__ __align__(8) int2 g_csr[EE];
__device__ __align__(16) float g_stats[DD+1];
__device__ __align__(16) float g_norm [DD+1];
__device__ int   g_bsum[256];
__device__ int   g_barcnt = 0;
__device__ int   g_bargen = 0;
__device__ int   g_done   = 0;

// ---- software grid barrier (all CSRB blocks resident) ----
__device__ __forceinline__ void grid_barrier() {
    __syncthreads();
    if (threadIdx.x == 0) {
        __threadfence();
        int gen = *(volatile int*)&g_bargen;
        if (atomicAdd(&g_barcnt, 1) == (int)gridDim.x - 1) {
            atomicExch(&g_barcnt, 0);
            __threadfence();
            atomicAdd(&g_bargen, 1);
        } else {
            while (*(volatile int*)&g_bargen == gen) { }
        }
        __threadfence();
    }
    __syncthreads();
}

// ---- bf16 split helpers ----
__device__ __forceinline__ void split2(float x0, float x1, uint32_t& hi, uint32_t& lo) {
    __nv_bfloat16 h0 = __float2bfloat16(x0);
    __nv_bfloat16 h1 = __float2bfloat16(x1);
    __nv_bfloat16 l0 = __float2bfloat16(x0 - __bfloat162float(h0));
    __nv_bfloat16 l1 = __float2bfloat16(x1 - __bfloat162float(h1));
    hi = (uint32_t)__bfloat16_as_ushort(h0) | ((uint32_t)__bfloat16_as_ushort(h1) << 16);
    lo = (uint32_t)__bfloat16_as_ushort(l0) | ((uint32_t)__bfloat16_as_ushort(l1) << 16);
}

// ---------------- fused CSR build + embedding + init ----------------
__global__ void __launch_bounds__(256) k_csr_build(const int*   __restrict__ ei,
                                                   const float* __restrict__ pos,
                                                   const float* __restrict__ hin,
                                                   const float* __restrict__ Wemb,
                                                   const float* __restrict__ bemb) {
    __shared__ int s[256];
    int tid = threadIdx.x;
    int bid = blockIdx.x;
    int gt  = bid * 256 + tid;

    if (gt < 64)  { g_norm[gt] = 0.f; g_stats[gt] = 0.f; }
    if (gt == 64) { g_norm[64] = 1.f; g_stats[64] = 0.f; g_done = 0; }
    if (gt < NN) g_cnt[gt] = 0;
    grid_barrier();

    for (int e = gt; e < EE; e += CSRB * 256)
        atomicAdd(&g_cnt[ei[EE + e]], 1);
    grid_barrier();

    {
        int c = (gt < NN) ? g_cnt[gt] : 0;
        s[tid] = c;
        __syncthreads();
        #pragma unroll
        for (int off = 1; off < 256; off <<= 1) {
            int t = 0;
            if (tid >= off) t = s[tid - off];
            __syncthreads();
            s[tid] += t;
            __syncthreads();
        }
        if (gt < NN) g_rowptr[gt] = s[tid] - c;
        if (tid == 255) g_bsum[bid] = s[255];
    }
    grid_barrier();

    if (bid == 0) {
        int c = (tid < CSRB) ? g_bsum[tid] : 0;
        s[tid] = c;
        __syncthreads();
        #pragma unroll
        for (int off = 1; off < 256; off <<= 1) {
            int t = 0;
            if (tid >= off) t = s[tid - off];
            __syncthreads();
            s[tid] += t;
            __syncthreads();
        }
        if (tid < CSRB) g_bsum[tid] = s[tid] - c;
    }
    grid_barrier();

    if (gt < NN) {
        int r = g_rowptr[gt] + g_bsum[bid];
        g_rowptr[gt] = r;
        g_cnt[gt] = r;
    }
    if (gt == 0) g_rowptr[NN] = EE;
    grid_barrier();

    for (int e = gt; e < EE; e += CSRB * 256) {
        int sn = ei[e];
        int d  = ei[EE + e];
        int p  = atomicAdd(&g_cnt[d], 1);
        float dx = pos[2*d]   - pos[2*sn];
        float dy = pos[2*d+1] - pos[2*sn+1];
        g_csr[p] = make_int2(sn, __float_as_int(sqrtf(dx*dx + dy*dy)));
    }

    int lane = tid & 31;
    int c0   = lane * 2;
    for (int w = gt >> 5; w < NN; w += (CSRB*256) >> 5) {
        float v0 = hin[w*5+0], v1 = hin[w*5+1], v2 = hin[w*5+2],
              v3 = hin[w*5+3], v4 = hin[w*5+4];
        #pragma unroll
        for (int j = 0; j < 2; j++) {
            int c = c0 + j;
            float acc = bemb[c] + v0*Wemb[c] + v1*Wemb[64+c] + v2*Wemb[128+c]
                                + v3*Wemb[192+c] + v4*Wemb[256+c];
            g_hr[w*64+c] = fmaxf(acc, 0.f);
        }
    }
}

// ---------------- wmma GEMM: [a|b] = pairnorm(hr) @ [Wa|Wb], bf16 split 3-term ----------------
// smem: Xh[128][XLD], Xl[128][XLD] bf16; Wh[64][WLD_AB], Wl[64][WLD_AB] bf16
#define AB_XH 0
#define AB_XL (128*XLD*2)
#define AB_WH (2*128*XLD*2)
#define AB_WL (2*128*XLD*2 + 64*WLD_AB*2)
#define AB_SMEM (2*128*XLD*2 + 2*64*WLD_AB*2)   // 75776 B

__global__ void __launch_bounds__(256) k_gemm_ab(const float* __restrict__ Wm) {
    extern __shared__ __align__(32) char smem[];
    __nv_bfloat16* sXh = (__nv_bfloat16*)(smem + AB_XH);
    __nv_bfloat16* sXl = (__nv_bfloat16*)(smem + AB_XL);
    __nv_bfloat16* sWh = (__nv_bfloat16*)(smem + AB_WH);
    __nv_bfloat16* sWl = (__nv_bfloat16*)(smem + AB_WL);
    int tid  = threadIdx.x;
    int base = blockIdx.x * 128;
    float inv = g_norm[64];

    // stage X (norm applied): 128 rows x 64 k
    #pragma unroll
    for (int it = 0; it < 8; it++) {
        int idx = tid + 256*it;          // 2048 float4
        int r   = idx >> 4;
        int cq  = idx & 15;
        int n   = base + r;
        float4 v = make_float4(0.f,0.f,0.f,0.f);
        if (n < NN) v = *(const float4*)&g_hr[n*64 + cq*4];
        float4 mu = *(const float4*)&g_norm[cq*4];
        v.x = (v.x - mu.x)*inv; v.y = (v.y - mu.y)*inv;
        v.z = (v.z - mu.z)*inv; v.w = (v.w - mu.w)*inv;
        uint32_t h0, l0, h1, l1;
        split2(v.x, v.y, h0, l0);
        split2(v.z, v.w, h1, l1);
        uint32_t* ph = (uint32_t*)&sXh[r*XLD + cq*4];
        uint32_t* pl = (uint32_t*)&sXl[r*XLD + cq*4];
        ph[0] = h0; ph[1] = h1;
        pl[0] = l0; pl[1] = l1;
    }
    // stage W remap: out col c<64 -> Wm[k][c]; c>=64 -> Wm[64+k][c-64]
    #pragma unroll
    for (int it = 0; it < 8; it++) {
        int idx = tid + 256*it;          // 2048 float4 over 64k x 128c
        int k   = idx >> 5;
        int cq  = idx & 31;
        int c0  = cq*4;
        const float* src = (cq < 16) ? &Wm[k*64 + c0] : &Wm[(64+k)*64 + (c0-64)];
        float4 v = *(const float4*)src;
        uint32_t h0, l0, h1, l1;
        split2(v.x, v.y, h0, l0);
        split2(v.z, v.w, h1, l1);
        uint32_t* ph = (uint32_t*)&sWh[k*WLD_AB + c0];
        uint32_t* pl = (uint32_t*)&sWl[k*WLD_AB + c0];
        ph[0] = h0; ph[1] = h1;
        pl[0] = l0; pl[1] = l1;
    }
    __syncthreads();

    int w  = tid >> 5;
    int wr = w & 3;                      // rows wr*32 .. +31 (2 m-tiles)
    int wc = w >> 2;                     // cols wc*64 .. +63 (4 n-tiles)
    wmma::fragment<wmma::accumulator, 16, 16, 16, float> acc[2][4];
    #pragma unroll
    for (int i = 0; i < 2; i++)
        #pragma unroll
        for (int j = 0; j < 4; j++) wmma::fill_fragment(acc[i][j], 0.f);

    #pragma unroll
    for (int k0 = 0; k0 < 64; k0 += 16) {
        #pragma unroll
        for (int cmb = 0; cmb < 3; cmb++) {
            const __nv_bfloat16* Xs = (cmb == 2) ? sXl : sXh;
            const __nv_bfloat16* Ws = (cmb == 1) ? sWl : sWh;
            wmma::fragment<wmma::matrix_a, 16, 16, 16, __nv_bfloat16, wmma::row_major> af[2];
            wmma::load_matrix_sync(af[0], &Xs[(wr*32     )*XLD + k0], XLD);
            wmma::load_matrix_sync(af[1], &Xs[(wr*32 + 16)*XLD + k0], XLD);
            #pragma unroll
            for (int j = 0; j < 4; j++) {
                wmma::fragment<wmma::matrix_b, 16, 16, 16, __nv_bfloat16, wmma::row_major> bf;
                wmma::load_matrix_sync(bf, &Ws[k0*WLD_AB + wc*64 + j*16], WLD_AB);
                wmma::mma_sync(acc[0][j], af[0], bf, acc[0][j]);
                wmma::mma_sync(acc[1][j], af[1], bf, acc[1][j]);
            }
        }
    }

    #pragma unroll
    for (int i = 0; i < 2; i++) {
        int gr = base + wr*32 + i*16;
        if (gr < NN) {                   // NN multiple of 16: tiles never straddle
            #pragma unroll
            for (int j = 0; j < 4; j++) {
                int gc = wc*64 + j*16;
                float* Out = (gc < 64) ? &g_a[gr*64 + gc] : &g_b[gr*64 + (gc - 64)];
                wmma::store_matrix_sync(Out, acc[i][j], 64, wmma::mem_row_major);
            }
        }
    }
}

// ---------------- per-node edge gather (MLP=8) ----------------
__global__ void __launch_bounds__(256) k_gather(const float* __restrict__ Wm,
                                                const float* __restrict__ bm) {
    int gw   = (blockIdx.x*blockDim.x + threadIdx.x) >> 5;
    int lane = threadIdx.x & 31;
    int c0 = lane*2;
    float wdx = Wm[128*64 + c0], wdy = Wm[128*64 + c0 + 1];
    float2 av = *(const float2*)&g_a[gw*64 + c0];
    float pax = av.x + bm[c0];
    float pay = av.y + bm[c0+1];
    float ax = 0.f, ay = 0.f;
    int st = g_rowptr[gw], en = g_rowptr[gw+1];

    for (int eb = st; eb < en; eb += 8) {
        int mm = en - eb; if (mm > 8) mm = 8;
        int2 ed = make_int2(0, 0);
        if (lane < mm) ed = g_csr[eb + lane];
        float2 bv[8];
        float  dv[8];
        #pragma unroll
        for (int j = 0; j < 8; j++) {
            int sidx = __shfl_sync(0xffffffffu, ed.x, j);
            int dbit = __shfl_sync(0xffffffffu, ed.y, j);
            dv[j] = __int_as_float(dbit);
            if (j < mm) bv[j] = *(const float2*)&g_b[sidx*64 + c0];
        }
        #pragma unroll
        for (int j = 0; j < 8; j++) {
            if (j < mm) {
                ax += fmaxf(pax + bv[j].x + dv[j]*wdx, 0.f);
                ay += fmaxf(pay + bv[j].y + dv[j]*wdy, 0.f);
            }
        }
    }
    *(float2*)&g_aggr[gw*64 + c0] = make_float2(ax, ay);
}

// ---------------- wmma update GEMM: h' = relu([norm(h)|aggr] @ Wu + bu) + stats + finalize ----------------
// smem: Xh/Xl [128][XLD] bf16 (per 64-k chunk), Wh/Wl [64][WLD_UP] bf16;
// epilogue fp32 out [128][OLD] overlays the X region after compute.
#define UP_XH 0
#define UP_XL (128*XLD*2)
#define UP_WH (2*128*XLD*2)
#define UP_WL (2*128*XLD*2 + 64*WLD_UP*2)
#define UP_SMEM (2*128*XLD*2 + 2*64*WLD_UP*2)   // 59392 B

__global__ void __launch_bounds__(256) k_gemm_upd(const float* __restrict__ Wu,
                                                  const float* __restrict__ bu) {
    extern __shared__ __align__(32) char smem[];
    __nv_bfloat16* sXh = (__nv_bfloat16*)(smem + UP_XH);
    __nv_bfloat16* sXl = (__nv_bfloat16*)(smem + UP_XL);
    __nv_bfloat16* sWh = (__nv_bfloat16*)(smem + UP_WH);
    __nv_bfloat16* sWl = (__nv_bfloat16*)(smem + UP_WL);
    float*         sO  = (float*)smem;          // overlay after compute (34816 <= 40960)
    __shared__ float sstats[65];
    int tid  = threadIdx.x;
    int base = blockIdx.x * 128;
    float inv = g_norm[64];
    int w = tid >> 5;                            // warp: rows w*16..+15, cols 0..63

    if (tid < 65) sstats[tid] = 0.f;

    wmma::fragment<wmma::accumulator, 16, 16, 16, float> acc[4];
    #pragma unroll
    for (int j = 0; j < 4; j++) wmma::fill_fragment(acc[j], 0.f);

    #pragma unroll
    for (int ch = 0; ch < 2; ch++) {
        __syncthreads();                         // protect X/W from previous iter readers
        const bool fromH = (ch == 0);
        const float* Xsrc = fromH ? g_hr : g_aggr;
        // stage X chunk
        #pragma unroll
        for (int it = 0; it < 8; it++) {
            int idx = tid + 256*it;
            int r   = idx >> 4;
            int cq  = idx & 15;
            int n   = base + r;
            float4 v = make_float4(0.f,0.f,0.f,0.f);
            if (n < NN) v = *(const float4*)&Xsrc[n*64 + cq*4];
            if (fromH) {
                float4 mu = *(const float4*)&g_norm[cq*4];
                v.x = (v.x - mu.x)*inv; v.y = (v.y - mu.y)*inv;
                v.z = (v.z - mu.z)*inv; v.w = (v.w - mu.w)*inv;
            }
            uint32_t h0, l0, h1, l1;
            split2(v.x, v.y, h0, l0);
            split2(v.z, v.w, h1, l1);
            uint32_t* ph = (uint32_t*)&sXh[r*XLD + cq*4];
            uint32_t* pl = (uint32_t*)&sXl[r*XLD + cq*4];
            ph[0] = h0; ph[1] = h1;
            pl[0] = l0; pl[1] = l1;
        }
        // stage W chunk (rows ch*64 .. +63)
        #pragma unroll
        for (int it = 0; it < 4; it++) {
            int idx = tid + 256*it;              // 1024 float4 over 64k x 64c
            int k   = idx >> 4;
            int cq  = idx & 15;
            float4 v = *(const float4*)&Wu[(ch*64 + k)*64 + cq*4];
            uint32_t h0, l0, h1, l1;
            split2(v.x, v.y, h0, l0);
            split2(v.z, v.w, h1, l1);
            uint32_t* ph = (uint32_t*)&sWh[k*WLD_UP + cq*4];
            uint32_t* pl = (uint32_t*)&sWl[k*WLD_UP + cq*4];
            ph[0] = h0; ph[1] = h1;
            pl[0] = l0; pl[1] = l1;
        }
        __syncthreads();

        #pragma unroll
        for (int k0 = 0; k0 < 64; k0 += 16) {
            #pragma unroll
            for (int cmb = 0; cmb < 3; cmb++) {
                const __nv_bfloat16* Xs = (cmb == 2) ? sXl : sXh;
                const __nv_bfloat16* Ws = (cmb == 1) ? sWl : sWh;
                wmma::fragment<wmma::matrix_a, 16, 16, 16, __nv_bfloat16, wmma::row_major> af;
                wmma::load_matrix_sync(af, &Xs[(w*16)*XLD + k0], XLD);
                #pragma unroll
                for (int j = 0; j < 4; j++) {
                    wmma::fragment<wmma::matrix_b, 16, 16, 16, __nv_bfloat16, wmma::row_major> bf;
                    wmma::load_matrix_sync(bf, &Ws[k0*WLD_UP + j*16], WLD_UP);
                    wmma::mma_sync(acc[j], af, bf, acc[j]);
                }
            }
        }
    }

    // park acc in smem (overlays X), then scalar epilogue
    __syncthreads();
    #pragma unroll
    for (int j = 0; j < 4; j++)
        wmma::store_matrix_sync(&sO[(w*16)*OLD + j*16], acc[j], OLD, wmma::mem_row_major);
    __syncthreads();

    {
        int cq = tid & 15;
        float4 bb = *(const float4*)&bu[cq*4];
        float ls[4] = {0.f,0.f,0.f,0.f};
        float lss = 0.f;
        #pragma unroll
        for (int it = 0; it < 8; it++) {
            int idx = tid + 256*it;
            int r   = idx >> 4;
            int n   = base + r;
            if (n < NN) {
                float4 v = *(const float4*)&sO[r*OLD + cq*4];
                float o0 = fmaxf(v.x + bb.x, 0.f);
                float o1 = fmaxf(v.y + bb.y, 0.f);
                float o2 = fmaxf(v.z + bb.z, 0.f);
                float o3 = fmaxf(v.w + bb.w, 0.f);
                ls[0] += o0; ls[1] += o1; ls[2] += o2; ls[3] += o3;
                lss += o0*o0 + o1*o1 + o2*o2 + o3*o3;
                *(float4*)&g_hr[n*64 + cq*4] = make_float4(o0, o1, o2, o3);
            }
        }
        atomicAdd(&sstats[cq*4 + 0], ls[0]);
        atomicAdd(&sstats[cq*4 + 1], ls[1]);
        atomicAdd(&sstats[cq*4 + 2], ls[2]);
        atomicAdd(&sstats[cq*4 + 3], ls[3]);
        atomicAdd(&sstats[64], lss);
    }
    __syncthreads();
    if (tid < 65) atomicAdd(&g_stats[tid], sstats[tid]);

    // last block finalizes g_norm, re-arms stats
    __shared__ int isLast;
    __threadfence();
    __syncthreads();
    if (tid == 0)
        isLast = (atomicAdd(&g_done, 1) == (int)gridDim.x - 1) ? 1 : 0;
    __syncthreads();
    if (isLast) {
        __shared__ float spart[2];
        if (tid < 64) {
            float mu = g_stats[tid] * (1.0f/NN);
            g_norm[tid] = mu;
            float m2 = mu*mu;
            #pragma unroll
            for (int off = 16; off > 0; off >>= 1)
                m2 += __shfl_down_sync(0xffffffffu, m2, off);
            if ((tid & 31) == 0) spart[tid >> 5] = m2;
        }
        __syncthreads();
        if (tid == 0) {
            float musq = spart[0] + spart[1];
            g_norm[64] = 1.0f / sqrtf(1e-5f + g_stats[64]*(1.0f/NN) - musq);
            g_done = 0;
        }
        __syncthreads();
        if (tid < 65) g_stats[tid] = 0.f;
    }
}

// ---------------- pool + tiny MLP ----------------
__global__ void k_pool(const float* __restrict__ W1, const float* __restrict__ b1,
                       const float* __restrict__ W2, const float* __restrict__ b2,
                       float* __restrict__ out) {
    __shared__ float red[4][64];
    __shared__ float hg[64];
    __shared__ float z[64];
    int g   = blockIdx.x;
    int tid = threadIdx.x;
    int c     = tid & 63;
    int chunk = tid >> 6;
    float m = -3.4e38f;
    int nbeg = g*NPG + chunk*(NPG/4);
    for (int i = 0; i < NPG/4; i++)
        m = fmaxf(m, g_hr[(nbeg + i)*64 + c]);
    red[chunk][c] = m;
    __syncthreads();
    if (tid < 64) {
        float mr = fmaxf(fmaxf(red[0][tid], red[1][tid]),
                         fmaxf(red[2][tid], red[3][tid]));
        hg[tid] = (mr - g_norm[tid]) * g_norm[64];   // pairnorm monotone per column
    }
    __syncthreads();
    if (tid < 64) {
        float acc = b1[tid];
        for (int k = 0; k < 64; k++) acc = fmaf(hg[k], W1[k*64 + tid], acc);
        z[tid] = fmaxf(acc, 0.f);
    }
    __syncthreads();
    if (tid < 2) {
        float acc = b2[tid];
        for (int k = 0; k < 64; k++) acc = fmaf(z[k], W2[k*2 + tid], acc);
        out[g*2 + tid] = acc;
    }
}

// ---------------- launch ----------------
extern "C" void kernel_launch(void* const* d_in, const int* in_sizes, int n_in,
                              void* d_out, int out_size) {
    const float* h_in = (const float*)d_in[0];
    const float* pos  = (const float*)d_in[1];
    const int*   ei   = (const int*)  d_in[2];
    // d_in[3] = batch — contiguous 1000-node graphs, unused
    const float* Wemb = (const float*)d_in[4];
    const float* bemb = (const float*)d_in[5];
    const float* msgW = (const float*)d_in[6];
    const float* msgb = (const float*)d_in[7];
    const float* updW = (const float*)d_in[8];
    const float* updb = (const float*)d_in[9];
    const float* W1   = (const float*)d_in[10];
    const float* b1   = (const float*)d_in[11];
    const float* W2   = (const float*)d_in[12];
    const float* b2   = (const float*)d_in[13];
    float* out = (float*)d_out;

    static int attr_done = 0;
    if (!attr_done) {
        cudaFuncSetAttribute(k_gemm_ab,  cudaFuncAttributeMaxDynamicSharedMemorySize, AB_SMEM);
        cudaFuncSetAttribute(k_gemm_upd, cudaFuncAttributeMaxDynamicSharedMemorySize, UP_SMEM);
        attr_done = 1;
    }

    k_csr_build<<<CSRB, 256>>>(ei, pos, h_in, Wemb, bemb);

    for (int l = 0; l < 2; l++) {
        const float* Wm = msgW + l*129*64;
        const float* bm = msgb + l*64;
        const float* Wu = updW + l*128*64;
        const float* bu = updb + l*64;
        k_gemm_ab <<<391, 256, AB_SMEM>>>(Wm);
        k_gather  <<<6250, 256>>>(Wm, bm);
        k_gemm_upd<<<391, 256, UP_SMEM>>>(Wu, bu);
    }

    k_pool<<<50, 256>>>(W1, b1, W2, b2, out);
}